// round 14
// baseline (speedup 1.0000x reference)
#include <cuda_runtime.h>
#include <cstdint>
#include <cstddef>

// ============================================================================
// SwinMSA round 13: GEMM M-tile 256 (512 thr, 16 warps, dyn smem 72KB) to
// halve B-weight LTS traffic. Pipeline/LDSM mechanics identical to the
// passing round-12 kernel; attention/prep unchanged.
// ============================================================================

namespace {
constexpr int HEADS = 16;
constexpr int HD    = 32;
constexpr int NT    = 64;
constexpr int BW    = 1024;
constexpr int CIN   = 512;
constexpr int CQKV  = 1536;
constexpr int KP    = CIN / 2;
constexpr float ATT_SCALE = 0.17677669529663688f;
// dynamic smem (uint32 offsets): A stages 256rows x 8, B stages 128rows x 8
constexpr int SA_ST = 2048;                 // u32 per A stage
constexpr int SB_ST = 1024;                 // u32 per B stage
constexpr int OFF_AH = 0;
constexpr int OFF_AL = 3 * SA_ST;           // 6144
constexpr int OFF_BH = 6 * SA_ST;           // 12288
constexpr int OFF_BL = OFF_BH + 3 * SB_ST;  // 15360
constexpr int SMEM_U32 = OFF_BL + 3 * SB_ST;   // 18432
constexpr int SMEM_BYTES = SMEM_U32 * 4;       // 73728
}

// -------- __device__ scratch (allocation-free rule) --------
__device__ float    g_Q[(size_t)BW * HEADS * NT * HD];
__device__ float    g_K[(size_t)BW * HEADS * NT * HD];
__device__ float    g_V[(size_t)BW * HEADS * NT * HD];
__device__ float    g_WqkvT[(size_t)CQKV * CIN];
__device__ float    g_WprojT[(size_t)CIN * CIN];
__device__ uint32_t g_Xhi[(size_t)BW * NT * KP],  g_Xlo[(size_t)BW * NT * KP];
__device__ uint32_t g_Ohi[(size_t)BW * NT * KP],  g_Olo[(size_t)BW * NT * KP];
__device__ uint32_t g_Wh0[(size_t)CQKV * KP],     g_Wl0[(size_t)CQKV * KP];
__device__ uint32_t g_Wh1[(size_t)CIN * KP],      g_Wl1[(size_t)CIN * KP];

__device__ __forceinline__ uint32_t smem_u32(const void* p) {
    uint32_t a;
    asm("{ .reg .u64 t; cvta.to.shared.u64 t, %1; cvt.u32.u64 %0, t; }"
        : "=r"(a) : "l"(p));
    return a;
}
__device__ __forceinline__ void cp_async16(uint32_t saddr, const void* gaddr) {
    asm volatile("cp.async.cg.shared.global [%0], [%1], 16;"
                 :: "r"(saddr), "l"(gaddr));
}
__device__ __forceinline__ void cp_commit() {
    asm volatile("cp.async.commit_group;");
}
template <int N>
__device__ __forceinline__ void cp_wait() {
    asm volatile("cp.async.wait_group %0;" :: "n"(N));
}
__device__ __forceinline__ void mma_tf32(float* d, const uint32_t* a,
                                         const uint32_t* b) {
    asm volatile(
        "mma.sync.aligned.m16n8k8.row.col.f32.tf32.tf32.f32 "
        "{%0,%1,%2,%3}, {%4,%5,%6,%7}, {%8,%9}, {%0,%1,%2,%3};"
        : "+f"(d[0]), "+f"(d[1]), "+f"(d[2]), "+f"(d[3])
        : "r"(a[0]), "r"(a[1]), "r"(a[2]), "r"(a[3]), "r"(b[0]), "r"(b[1]));
}
__device__ __forceinline__ void mma_bf16(float* d, const uint32_t* a,
                                         const uint32_t* b) {
    asm volatile(
        "mma.sync.aligned.m16n8k16.row.col.f32.bf16.bf16.f32 "
        "{%0,%1,%2,%3}, {%4,%5,%6,%7}, {%8,%9}, {%0,%1,%2,%3};"
        : "+f"(d[0]), "+f"(d[1]), "+f"(d[2]), "+f"(d[3])
        : "r"(a[0]), "r"(a[1]), "r"(a[2]), "r"(a[3]), "r"(b[0]), "r"(b[1]));
}
__device__ __forceinline__ void ldsm_x4(uint32_t* r, uint32_t addr) {
    asm volatile("ldmatrix.sync.aligned.m8n8.x4.shared.b16 {%0,%1,%2,%3}, [%4];"
                 : "=r"(r[0]), "=r"(r[1]), "=r"(r[2]), "=r"(r[3]) : "r"(addr));
}
__device__ __forceinline__ void ldsm_x2(uint32_t* r, uint32_t addr) {
    asm volatile("ldmatrix.sync.aligned.m8n8.x2.shared.b16 {%0,%1}, [%2];"
                 : "=r"(r[0]), "=r"(r[1]) : "r"(addr));
}
__device__ __forceinline__ void bf16_split2(float2 f, uint32_t& hi, uint32_t& lo) {
    asm("cvt.rn.bf16x2.f32 %0, %1, %2;" : "=r"(hi) : "f"(f.y), "f"(f.x));
    float xr = f.x - __uint_as_float(hi << 16);
    float yr = f.y - __uint_as_float(hi & 0xffff0000u);
    asm("cvt.rn.bf16x2.f32 %0, %1, %2;" : "=r"(lo) : "f"(yr), "f"(xr));
}

// ----------------------------------------------------------------------------
// W transpose: W [K=512, C] row-major -> dst [C, 512] K-major
// ----------------------------------------------------------------------------
template <int MODE>
__global__ void transpose_w(const float* __restrict__ W) {
    const int C = (MODE == 0) ? CQKV : CIN;
    float* dst = (MODE == 0) ? g_WqkvT : g_WprojT;
    __shared__ float t[32][33];
    const int x  = blockIdx.x * 32 + threadIdx.x;
    const int y0 = blockIdx.y * 32;
    #pragma unroll
    for (int j = 0; j < 32; j += 8)
        t[threadIdx.y + j][threadIdx.x] = W[(size_t)(y0 + threadIdx.y + j) * C + x];
    __syncthreads();
    const int ox  = y0 + threadIdx.x;
    const int oy0 = blockIdx.x * 32;
    #pragma unroll
    for (int j = 0; j < 32; j += 8)
        dst[(size_t)(oy0 + threadIdx.y + j) * CIN + ox] = t[threadIdx.x][threadIdx.y + j];
}

// ----------------------------------------------------------------------------
// Split fp32 stream into packed bf16x2 hi/lo
// ----------------------------------------------------------------------------
__global__ void split_kernel(const float* __restrict__ src,
                             uint32_t* __restrict__ hi,
                             uint32_t* __restrict__ lo, int n4) {
    const int i = blockIdx.x * blockDim.x + threadIdx.x;
    if (i >= n4) return;
    float4 v = ((const float4*)src)[i];
    uint32_t h0, l0, h1, l1;
    bf16_split2(make_float2(v.x, v.y), h0, l0);
    bf16_split2(make_float2(v.z, v.w), h1, l1);
    ((uint2*)hi)[i] = make_uint2(h0, h1);
    ((uint2*)lo)[i] = make_uint2(l0, l1);
}

// ----------------------------------------------------------------------------
// bf16x3 GEMM, pre-split operands. C[M,N] = A @ B^T.
// CTA 256x128, 512 threads (16 warps: 4M x 4N), warp tile 64x32, K-chunk 16.
// 3-stage cp.async pipeline, LDSM fragments, dynamic smem (72KB).
// ----------------------------------------------------------------------------
template <int MODE>
__global__ __launch_bounds__(512, 1)
void gemm_mma(const float* __restrict__ bias, float* __restrict__ Out) {
    extern __shared__ uint32_t dyn[];

    const uint32_t* Ahi = MODE ? g_Ohi : g_Xhi;
    const uint32_t* Alo = MODE ? g_Olo : g_Xlo;
    const uint32_t* Bhi = MODE ? g_Wh1 : g_Wh0;
    const uint32_t* Blo = MODE ? g_Wl1 : g_Wl0;

    const int tid   = threadIdx.x;
    const int wid   = tid >> 5;
    const int lane  = tid & 31;
    const int warpM = wid >> 2;           // 0..3 -> 64 rows each
    const int warpN = wid & 3;            // 0..3 -> 32 cols each
    const int r4    = lane >> 2;
    const int c4    = lane & 3;
    const int M0    = blockIdx.y * 256;
    const int N0    = blockIdx.x * 128;

    // smem base addresses (byte)
    const uint32_t aAh = smem_u32(dyn + OFF_AH);
    const uint32_t aAl = smem_u32(dyn + OFF_AL);
    const uint32_t aBh = smem_u32(dyn + OFF_BH);
    const uint32_t aBl = smem_u32(dyn + OFF_BL);

    // loaders: A — all 512 threads (256 rows x 2 halves); B — tid<256
    const int arow = tid >> 1, ahalf = tid & 1;
    const uint32_t soffA =
        (uint32_t)(arow * 8 + ((ahalf ^ ((arow >> 2) & 1)) << 2)) * 4u;
    const size_t gAo = (size_t)(M0 + arow) * KP + ahalf * 4;
    const int brow = (tid & 255) >> 1, bhalf = tid & 1;
    const uint32_t soffB =
        (uint32_t)(brow * 8 + ((bhalf ^ ((brow >> 2) & 1)) << 2)) * 4u;
    const size_t gBo = (size_t)(N0 + brow) * KP + bhalf * 4;
    const bool doB = (tid < 256);

    // ldmatrix offsets: mt/nt deltas are constant (swizzle parity invariant)
    const int arow0 = warpM * 64 + (lane & 15);
    const uint32_t offA0 =
        (uint32_t)(arow0 * 8 + ((((lane >> 4) & 1) ^ ((arow0 >> 2) & 1)) << 2)) * 4u;
    const int brow0 = warpN * 32 + (lane & 7);
    const uint32_t offB0 =
        (uint32_t)(brow0 * 8 + ((((lane >> 3) & 1) ^ ((brow0 >> 2) & 1)) << 2)) * 4u;

    float acc[4][4][4] = {};

    // prologue: chunks 0,1 -> stages 0,1
    #pragma unroll
    for (int s = 0; s < 2; ++s) {
        cp_async16(aAh + s * (SA_ST * 4) + soffA, Ahi + gAo + s * 8);
        cp_async16(aAl + s * (SA_ST * 4) + soffA, Alo + gAo + s * 8);
        if (doB) {
            cp_async16(aBh + s * (SB_ST * 4) + soffB, Bhi + gBo + s * 8);
            cp_async16(aBl + s * (SB_ST * 4) + soffB, Blo + gBo + s * 8);
        }
        cp_commit();
    }

    int cur = 0;
    for (int c = 0; c < 32; ++c) {
        if (c + 2 < 32) cp_wait<1>();
        else            cp_wait<0>();
        __syncthreads();

        const uint32_t bAh = aAh + cur * (SA_ST * 4) + offA0;
        const uint32_t bAl = aAl + cur * (SA_ST * 4) + offA0;
        const uint32_t bBh = aBh + cur * (SB_ST * 4) + offB0;
        const uint32_t bBl = aBl + cur * (SB_ST * 4) + offB0;

        uint32_t ah[4][4], al[4][4];
        #pragma unroll
        for (int mt = 0; mt < 4; ++mt) {
            ldsm_x4(ah[mt], bAh + mt * 512u);
            ldsm_x4(al[mt], bAl + mt * 512u);
        }
        #pragma unroll
        for (int nt = 0; nt < 4; ++nt) {
            uint32_t bh[2], bl[2];
            ldsm_x2(bh, bBh + nt * 256u);
            ldsm_x2(bl, bBl + nt * 256u);
            #pragma unroll
            for (int mt = 0; mt < 4; ++mt)
                mma_bf16(acc[mt][nt], ah[mt], bh);
            #pragma unroll
            for (int mt = 0; mt < 4; ++mt)
                mma_bf16(acc[mt][nt], ah[mt], bl);
            #pragma unroll
            for (int mt = 0; mt < 4; ++mt)
                mma_bf16(acc[mt][nt], al[mt], bh);
        }

        if (c + 2 < 32) {
            const int nb = (cur + 2 >= 3) ? cur - 1 : cur + 2;
            const int kt = (c + 2) * 8;
            cp_async16(aAh + nb * (SA_ST * 4) + soffA, Ahi + gAo + kt);
            cp_async16(aAl + nb * (SA_ST * 4) + soffA, Alo + gAo + kt);
            if (doB) {
                cp_async16(aBh + nb * (SB_ST * 4) + soffB, Bhi + gBo + kt);
                cp_async16(aBl + nb * (SB_ST * 4) + soffB, Blo + gBo + kt);
            }
            cp_commit();
        }
        cur = (cur + 1 >= 3) ? 0 : cur + 1;
    }

    // ---- epilogue ----
    #pragma unroll
    for (int nt = 0; nt < 4; ++nt) {
        const int c0 = N0 + warpN * 32 + nt * 8 + c4 * 2;
        const float2 bv = *(const float2*)&bias[c0];
        if (MODE == 0) {
            const int h   = c0 / 96;
            const int rem = c0 - h * 96;
            const int sel = rem >> 5;
            const int d   = rem & 31;
            float* dst = (sel == 0) ? g_Q : (sel == 1) ? g_K : g_V;
            const float m = (sel == 0) ? ATT_SCALE : 1.0f;
            #pragma unroll
            for (int mt = 0; mt < 4; ++mt)
                #pragma unroll
                for (int hh = 0; hh < 2; ++hh) {
                    const int t = M0 + warpM * 64 + mt * 16 + r4 + hh * 8;
                    const int bwin = t >> 6, n = t & 63;
                    const size_t off =
                        ((size_t)(bwin * HEADS + h) * NT + n) * HD + d;
                    float2 o;
                    o.x = (acc[mt][nt][hh * 2 + 0] + bv.x) * m;
                    o.y = (acc[mt][nt][hh * 2 + 1] + bv.y) * m;
                    *(float2*)&dst[off] = o;
                }
        } else {
            #pragma unroll
            for (int mt = 0; mt < 4; ++mt)
                #pragma unroll
                for (int hh = 0; hh < 2; ++hh) {
                    const int t = M0 + warpM * 64 + mt * 16 + r4 + hh * 8;
                    float2 o;
                    o.x = acc[mt][nt][hh * 2 + 0] + bv.x;
                    o.y = acc[mt][nt][hh * 2 + 1] + bv.y;
                    *(float2*)&Out[(size_t)t * CIN + c0] = o;
                }
        }
    }
}

// ----------------------------------------------------------------------------
// Attention (unchanged from passing round 12).
// ----------------------------------------------------------------------------
__global__ __launch_bounds__(128)
void attn_kernel(const float* __restrict__ mask,
                 const float* __restrict__ bias_table,
                 const int*   __restrict__ rel_index)
{
    __shared__ float    Qs[64 * 36];
    __shared__ float    Ks[64 * 36];
    __shared__ uint32_t VtHi[32 * 36];
    __shared__ uint32_t VtLo[32 * 36];

    const int bid = blockIdx.x;
    const int b   = bid >> 4;
    const int h   = bid & 15;
    const int w   = b & 255;
    const int tid = threadIdx.x;
    const int wid = tid >> 5, lane = tid & 31;
    const int r4  = lane >> 2, c4 = lane & 3;

    const float* qp = g_Q + (size_t)bid * (NT * HD);
    const float* kp = g_K + (size_t)bid * (NT * HD);
    const float* vp = g_V + (size_t)bid * (NT * HD);

    {
        const int row = tid >> 1, half = (tid & 1) << 4;
        #pragma unroll
        for (int i = 0; i < 4; ++i) {
            *(float4*)&Qs[row * 36 + half + 4 * i] =
                *(const float4*)(qp + row * 32 + half + 4 * i);
            *(float4*)&Ks[row * 36 + half + 4 * i] =
                *(const float4*)(kp + row * 32 + half + 4 * i);
        }
        const int jp = tid >> 2, d0 = (tid & 3) << 3;
        float4 v00 = *(const float4*)(vp + (2 * jp) * 32 + d0);
        float4 v01 = *(const float4*)(vp + (2 * jp) * 32 + d0 + 4);
        float4 v10 = *(const float4*)(vp + (2 * jp + 1) * 32 + d0);
        float4 v11 = *(const float4*)(vp + (2 * jp + 1) * 32 + d0 + 4);
        uint32_t hh, ll;
        bf16_split2(make_float2(v00.x, v10.x), hh, ll);
        VtHi[(d0 + 0) * 36 + jp] = hh; VtLo[(d0 + 0) * 36 + jp] = ll;
        bf16_split2(make_float2(v00.y, v10.y), hh, ll);
        VtHi[(d0 + 1) * 36 + jp] = hh; VtLo[(d0 + 1) * 36 + jp] = ll;
        bf16_split2(make_float2(v00.z, v10.z), hh, ll);
        VtHi[(d0 + 2) * 36 + jp] = hh; VtLo[(d0 + 2) * 36 + jp] = ll;
        bf16_split2(make_float2(v00.w, v10.w), hh, ll);
        VtHi[(d0 + 3) * 36 + jp] = hh; VtLo[(d0 + 3) * 36 + jp] = ll;
        bf16_split2(make_float2(v01.x, v11.x), hh, ll);
        VtHi[(d0 + 4) * 36 + jp] = hh; VtLo[(d0 + 4) * 36 + jp] = ll;
        bf16_split2(make_float2(v01.y, v11.y), hh, ll);
        VtHi[(d0 + 5) * 36 + jp] = hh; VtLo[(d0 + 5) * 36 + jp] = ll;
        bf16_split2(make_float2(v01.z, v11.z), hh, ll);
        VtHi[(d0 + 6) * 36 + jp] = hh; VtLo[(d0 + 6) * 36 + jp] = ll;
        bf16_split2(make_float2(v01.w, v11.w), hh, ll);
        VtHi[(d0 + 7) * 36 + jp] = hh; VtLo[(d0 + 7) * 36 + jp] = ll;
    }
    __syncthreads();

    const int rm = wid * 16;
    const int i0 = rm + r4, i1 = i0 + 8;
    float acc[8][4] = {};
    #pragma unroll
    for (int kk = 0; kk < 4; ++kk) {
        uint32_t a[4];
        const uint32_t* pa = (const uint32_t*)&Qs[(rm + r4) * 36 + kk * 8 + c4];
        a[0] = pa[0]; a[1] = pa[8 * 36]; a[2] = pa[4]; a[3] = pa[8 * 36 + 4];
        #pragma unroll
        for (int nt = 0; nt < 8; ++nt) {
            const uint32_t* pb =
                (const uint32_t*)&Ks[(nt * 8 + r4) * 36 + kk * 8 + c4];
            uint32_t bf[2] = { pb[0], pb[4] };
            mma_tf32(acc[nt], a, bf);
        }
    }

    #pragma unroll
    for (int nt = 0; nt < 8; ++nt) {
        const int jc = nt * 8 + 2 * c4;
        const int2 rI0 = *(const int2*)&rel_index[i0 * 64 + jc];
        const int2 rI1 = *(const int2*)&rel_index[i1 * 64 + jc];
        const float2 m0 = *(const float2*)&mask[((size_t)w * 64 + i0) * 64 + jc];
        const float2 m1 = *(const float2*)&mask[((size_t)w * 64 + i1) * 64 + jc];
        acc[nt][0] += bias_table[rI0.x * HEADS + h] + m0.x;
        acc[nt][1] += bias_table[rI0.y * HEADS + h] + m0.y;
        acc[nt][2] += bias_table[rI1.x * HEADS + h] + m1.x;
        acc[nt][3] += bias_table[rI1.y * HEADS + h] + m1.y;
    }

    float mx0 = -3.0e38f, mx1 = -3.0e38f;
    #pragma unroll
    for (int nt = 0; nt < 8; ++nt) {
        mx0 = fmaxf(mx0, fmaxf(acc[nt][0], acc[nt][1]));
        mx1 = fmaxf(mx1, fmaxf(acc[nt][2], acc[nt][3]));
    }
    mx0 = fmaxf(mx0, __shfl_xor_sync(0xffffffffu, mx0, 1));
    mx0 = fmaxf(mx0, __shfl_xor_sync(0xffffffffu, mx0, 2));
    mx1 = fmaxf(mx1, __shfl_xor_sync(0xffffffffu, mx1, 1));
    mx1 = fmaxf(mx1, __shfl_xor_sync(0xffffffffu, mx1, 2));
    float s0 = 0.0f, s1 = 0.0f;
    #pragma unroll
    for (int nt = 0; nt < 8; ++nt) {
        acc[nt][0] = __expf(acc[nt][0] - mx0); s0 += acc[nt][0];
        acc[nt][1] = __expf(acc[nt][1] - mx0); s0 += acc[nt][1];
        acc[nt][2] = __expf(acc[nt][2] - mx1); s1 += acc[nt][2];
        acc[nt][3] = __expf(acc[nt][3] - mx1); s1 += acc[nt][3];
    }
    s0 += __shfl_xor_sync(0xffffffffu, s0, 1);
    s0 += __shfl_xor_sync(0xffffffffu, s0, 2);
    s1 += __shfl_xor_sync(0xffffffffu, s1, 1);
    s1 += __shfl_xor_sync(0xffffffffu, s1, 2);
    const float inv0 = 1.0f / s0, inv1 = 1.0f / s1;

    uint32_t ph[4][4], pl[4][4];
    #pragma unroll
    for (int ks = 0; ks < 4; ++ks) {
        bf16_split2(make_float2(acc[2 * ks][0] * inv0, acc[2 * ks][1] * inv0),
                    ph[ks][0], pl[ks][0]);
        bf16_split2(make_float2(acc[2 * ks][2] * inv1, acc[2 * ks][3] * inv1),
                    ph[ks][1], pl[ks][1]);
        bf16_split2(make_float2(acc[2 * ks + 1][0] * inv0, acc[2 * ks + 1][1] * inv0),
                    ph[ks][2], pl[ks][2]);
        bf16_split2(make_float2(acc[2 * ks + 1][2] * inv1, acc[2 * ks + 1][3] * inv1),
                    ph[ks][3], pl[ks][3]);
    }

    float acc2[4][4] = {};
    #pragma unroll
    for (int ks = 0; ks < 4; ++ks) {
        #pragma unroll
        for (int nt2 = 0; nt2 < 4; ++nt2) {
            const int vr = (nt2 * 8 + r4) * 36 + ks * 8 + c4;
            uint32_t bh[2] = { VtHi[vr], VtHi[vr + 4] };
            uint32_t bl[2] = { VtLo[vr], VtLo[vr + 4] };
            mma_bf16(acc2[nt2], ph[ks], bh);
            mma_bf16(acc2[nt2], ph[ks], bl);
            mma_bf16(acc2[nt2], pl[ks], bh);
        }
    }

    #pragma unroll
    for (int nt2 = 0; nt2 < 4; ++nt2) {
        const int d0 = nt2 * 8 + 2 * c4;
        const int kpair = h * 16 + (d0 >> 1);
        uint32_t hh, ll;
        bf16_split2(make_float2(acc2[nt2][0], acc2[nt2][1]), hh, ll);
        g_Ohi[((size_t)b * NT + i0) * KP + kpair] = hh;
        g_Olo[((size_t)b * NT + i0) * KP + kpair] = ll;
        bf16_split2(make_float2(acc2[nt2][2], acc2[nt2][3]), hh, ll);
        g_Ohi[((size_t)b * NT + i1) * KP + kpair] = hh;
        g_Olo[((size_t)b * NT + i1) * KP + kpair] = ll;
    }
}

// ----------------------------------------------------------------------------
extern "C" void kernel_launch(void* const* d_in, const int* in_sizes, int n_in,
                              void* d_out, int out_size)
{
    (void)in_sizes; (void)n_in; (void)out_size;
    const float* x          = (const float*)d_in[0];
    const float* mask       = (const float*)d_in[1];
    const float* qkv_w      = (const float*)d_in[2];
    const float* qkv_b      = (const float*)d_in[3];
    const float* proj_w     = (const float*)d_in[4];
    const float* proj_b     = (const float*)d_in[5];
    const float* bias_table = (const float*)d_in[6];
    const int*   rel_index  = (const int*)d_in[7];
    float* out = (float*)d_out;

    uint32_t *xhi, *xlo, *wh0, *wl0, *wh1, *wl1;
    float *wqkvT, *wprojT;
    cudaGetSymbolAddress((void**)&xhi, g_Xhi);
    cudaGetSymbolAddress((void**)&xlo, g_Xlo);
    cudaGetSymbolAddress((void**)&wh0, g_Wh0);
    cudaGetSymbolAddress((void**)&wl0, g_Wl0);
    cudaGetSymbolAddress((void**)&wh1, g_Wh1);
    cudaGetSymbolAddress((void**)&wl1, g_Wl1);
    cudaGetSymbolAddress((void**)&wqkvT, g_WqkvT);
    cudaGetSymbolAddress((void**)&wprojT, g_WprojT);

    cudaFuncSetAttribute((const void*)gemm_mma<0>,
                         cudaFuncAttributeMaxDynamicSharedMemorySize, SMEM_BYTES);
    cudaFuncSetAttribute((const void*)gemm_mma<1>,
                         cudaFuncAttributeMaxDynamicSharedMemorySize, SMEM_BYTES);

    transpose_w<0><<<dim3(48, 16), dim3(32, 8)>>>(qkv_w);
    transpose_w<1><<<dim3(16, 16), dim3(32, 8)>>>(proj_w);
    split_kernel<<<32768, 256>>>(x, xhi, xlo, BW * NT * CIN / 4);
    split_kernel<<<768, 256>>>(wqkvT, wh0, wl0, CQKV * CIN / 4);
    split_kernel<<<256, 256>>>(wprojT, wh1, wl1, CIN * CIN / 4);
    gemm_mma<0><<<dim3(12, 256), 512, SMEM_BYTES>>>(qkv_b, nullptr);
    attn_kernel<<<BW * HEADS, 128>>>(mask, bias_table, rel_index);
    gemm_mma<1><<<dim3(4, 256), 512, SMEM_BYTES>>>(proj_b, out);
}

// round 17
// speedup vs baseline: 1.0996x; 1.0996x over previous
#include <cuda_runtime.h>
#include <cstdint>
#include <cstddef>

// ============================================================================
// SwinMSA round 14: revert to round-12 base (1305us); GEMM K-chunk 32 with
// 3-stage pipeline in 96KB dynamic smem (2 CTA/SM preserved, 16 syncs/CTA).
// 64B rows, 4-way block swizzle phys = kb ^ ((row>>1)&3).
// ============================================================================

namespace {
constexpr int HEADS = 16;
constexpr int HD    = 32;
constexpr int NT    = 64;
constexpr int BW    = 1024;
constexpr int CIN   = 512;
constexpr int CQKV  = 1536;
constexpr int KP    = CIN / 2;
constexpr float ATT_SCALE = 0.17677669529663688f;
// GEMM smem: per stage per tensor 128 rows x 16 u32 (64B rows)
constexpr int ST_U32  = 2048;                 // u32 per stage per tensor
constexpr int OFF_AH  = 0;
constexpr int OFF_AL  = 3 * ST_U32;
constexpr int OFF_BH  = 6 * ST_U32;
constexpr int OFF_BL  = 9 * ST_U32;
constexpr int SMEM_BYTES = 12 * ST_U32 * 4;   // 98304
}

// -------- __device__ scratch (allocation-free rule) --------
__device__ float    g_Q[(size_t)BW * HEADS * NT * HD];
__device__ float    g_K[(size_t)BW * HEADS * NT * HD];
__device__ float    g_V[(size_t)BW * HEADS * NT * HD];
__device__ float    g_WqkvT[(size_t)CQKV * CIN];
__device__ float    g_WprojT[(size_t)CIN * CIN];
__device__ uint32_t g_Xhi[(size_t)BW * NT * KP],  g_Xlo[(size_t)BW * NT * KP];
__device__ uint32_t g_Ohi[(size_t)BW * NT * KP],  g_Olo[(size_t)BW * NT * KP];
__device__ uint32_t g_Wh0[(size_t)CQKV * KP],     g_Wl0[(size_t)CQKV * KP];
__device__ uint32_t g_Wh1[(size_t)CIN * KP],      g_Wl1[(size_t)CIN * KP];

__device__ __forceinline__ uint32_t smem_u32(const void* p) {
    uint32_t a;
    asm("{ .reg .u64 t; cvta.to.shared.u64 t, %1; cvt.u32.u64 %0, t; }"
        : "=r"(a) : "l"(p));
    return a;
}
__device__ __forceinline__ void cp_async16(uint32_t saddr, const void* gaddr) {
    asm volatile("cp.async.cg.shared.global [%0], [%1], 16;"
                 :: "r"(saddr), "l"(gaddr));
}
__device__ __forceinline__ void cp_commit() {
    asm volatile("cp.async.commit_group;");
}
template <int N>
__device__ __forceinline__ void cp_wait() {
    asm volatile("cp.async.wait_group %0;" :: "n"(N));
}
__device__ __forceinline__ void mma_tf32(float* d, const uint32_t* a,
                                         const uint32_t* b) {
    asm volatile(
        "mma.sync.aligned.m16n8k8.row.col.f32.tf32.tf32.f32 "
        "{%0,%1,%2,%3}, {%4,%5,%6,%7}, {%8,%9}, {%0,%1,%2,%3};"
        : "+f"(d[0]), "+f"(d[1]), "+f"(d[2]), "+f"(d[3])
        : "r"(a[0]), "r"(a[1]), "r"(a[2]), "r"(a[3]), "r"(b[0]), "r"(b[1]));
}
__device__ __forceinline__ void mma_bf16(float* d, const uint32_t* a,
                                         const uint32_t* b) {
    asm volatile(
        "mma.sync.aligned.m16n8k16.row.col.f32.bf16.bf16.f32 "
        "{%0,%1,%2,%3}, {%4,%5,%6,%7}, {%8,%9}, {%0,%1,%2,%3};"
        : "+f"(d[0]), "+f"(d[1]), "+f"(d[2]), "+f"(d[3])
        : "r"(a[0]), "r"(a[1]), "r"(a[2]), "r"(a[3]), "r"(b[0]), "r"(b[1]));
}
__device__ __forceinline__ void ldsm_x4(uint32_t* r, uint32_t addr) {
    asm volatile("ldmatrix.sync.aligned.m8n8.x4.shared.b16 {%0,%1,%2,%3}, [%4];"
                 : "=r"(r[0]), "=r"(r[1]), "=r"(r[2]), "=r"(r[3]) : "r"(addr));
}
__device__ __forceinline__ void ldsm_x2(uint32_t* r, uint32_t addr) {
    asm volatile("ldmatrix.sync.aligned.m8n8.x2.shared.b16 {%0,%1}, [%2];"
                 : "=r"(r[0]), "=r"(r[1]) : "r"(addr));
}
__device__ __forceinline__ void bf16_split2(float2 f, uint32_t& hi, uint32_t& lo) {
    asm("cvt.rn.bf16x2.f32 %0, %1, %2;" : "=r"(hi) : "f"(f.y), "f"(f.x));
    float xr = f.x - __uint_as_float(hi << 16);
    float yr = f.y - __uint_as_float(hi & 0xffff0000u);
    asm("cvt.rn.bf16x2.f32 %0, %1, %2;" : "=r"(lo) : "f"(yr), "f"(xr));
}

// ----------------------------------------------------------------------------
// W transpose: W [K=512, C] row-major -> dst [C, 512] K-major
// ----------------------------------------------------------------------------
template <int MODE>
__global__ void transpose_w(const float* __restrict__ W) {
    const int C = (MODE == 0) ? CQKV : CIN;
    float* dst = (MODE == 0) ? g_WqkvT : g_WprojT;
    __shared__ float t[32][33];
    const int x  = blockIdx.x * 32 + threadIdx.x;
    const int y0 = blockIdx.y * 32;
    #pragma unroll
    for (int j = 0; j < 32; j += 8)
        t[threadIdx.y + j][threadIdx.x] = W[(size_t)(y0 + threadIdx.y + j) * C + x];
    __syncthreads();
    const int ox  = y0 + threadIdx.x;
    const int oy0 = blockIdx.x * 32;
    #pragma unroll
    for (int j = 0; j < 32; j += 8)
        dst[(size_t)(oy0 + threadIdx.y + j) * CIN + ox] = t[threadIdx.x][threadIdx.y + j];
}

// ----------------------------------------------------------------------------
// Split fp32 stream into packed bf16x2 hi/lo
// ----------------------------------------------------------------------------
__global__ void split_kernel(const float* __restrict__ src,
                             uint32_t* __restrict__ hi,
                             uint32_t* __restrict__ lo, int n4) {
    const int i = blockIdx.x * blockDim.x + threadIdx.x;
    if (i >= n4) return;
    float4 v = ((const float4*)src)[i];
    uint32_t h0, l0, h1, l1;
    bf16_split2(make_float2(v.x, v.y), h0, l0);
    bf16_split2(make_float2(v.z, v.w), h1, l1);
    ((uint2*)hi)[i] = make_uint2(h0, h1);
    ((uint2*)lo)[i] = make_uint2(l0, l1);
}

// ----------------------------------------------------------------------------
// bf16x3 GEMM, pre-split operands. C[M,N] = A @ B^T.
// CTA 128x128, 8 warps (2M x 4N), warp tile 64x32, K-chunk 32 (2x k16 sub).
// 3-stage cp.async pipeline (96KB dyn smem), LDSM fragments.
// smem rows: 16 u32 (64B); block swizzle phys = kb ^ ((row>>1)&3).
// ----------------------------------------------------------------------------
template <int MODE>
__global__ __launch_bounds__(256, 2)
void gemm_mma(const float* __restrict__ bias, float* __restrict__ Out) {
    extern __shared__ uint32_t dyn[];

    const uint32_t* Ahi = MODE ? g_Ohi : g_Xhi;
    const uint32_t* Alo = MODE ? g_Olo : g_Xlo;
    const uint32_t* Bhi = MODE ? g_Wh1 : g_Wh0;
    const uint32_t* Blo = MODE ? g_Wl1 : g_Wl0;

    const int tid   = threadIdx.x;
    const int wid   = tid >> 5;
    const int lane  = tid & 31;
    const int warpM = wid >> 2;
    const int warpN = wid & 3;
    const int r4    = lane >> 2;
    const int c4    = lane & 3;
    const int M0    = blockIdx.y * 128;
    const int N0    = blockIdx.x * 128;

    const uint32_t aAh = smem_u32(dyn + OFF_AH);
    const uint32_t aAl = smem_u32(dyn + OFF_AL);
    const uint32_t aBh = smem_u32(dyn + OFF_BH);
    const uint32_t aBl = smem_u32(dyn + OFF_BL);

    // loader: thread -> row = tid>>1 (0..127), kpair half ks8 = (tid&1)*8;
    // two 16B blocks per tensor: blocks b = ks8/4 + i, swizzled.
    const int lrow = tid >> 1, ks8 = (tid & 1) * 8;
    const int lswz = (lrow >> 1) & 3;
    uint32_t soff[2];
    #pragma unroll
    for (int i = 0; i < 2; ++i)
        soff[i] = (uint32_t)(lrow * 64 + (((ks8 >> 2) + i) ^ lswz) * 16);
    const size_t gAo = (size_t)(M0 + lrow) * KP + ks8;
    const size_t gBo = (size_t)(N0 + lrow) * KP + ks8;

    // fragment ldmatrix offsets, one per k16 subchunk kk2
    const int arow0 = warpM * 64 + (lane & 15);
    const int aswz  = (arow0 >> 1) & 3;
    const int ahl   = (lane >> 4) & 1;
    const int brow0 = warpN * 32 + (lane & 7);
    const int bswz  = (brow0 >> 1) & 3;
    const int bhl   = (lane >> 3) & 1;
    uint32_t offA[2], offB[2];
    #pragma unroll
    for (int kk2 = 0; kk2 < 2; ++kk2) {
        offA[kk2] = (uint32_t)(arow0 * 64 + ((kk2 * 2 + ahl) ^ aswz) * 16);
        offB[kk2] = (uint32_t)(brow0 * 64 + ((kk2 * 2 + bhl) ^ bswz) * 16);
    }

    float acc[4][4][4] = {};

    // prologue: chunks 0,1 -> stages 0,1
    #pragma unroll
    for (int s = 0; s < 2; ++s) {
        const int kt = s * 16;
        #pragma unroll
        for (int i = 0; i < 2; ++i) {
            cp_async16(aAh + s * (ST_U32 * 4) + soff[i], Ahi + gAo + kt + 4 * i);
            cp_async16(aAl + s * (ST_U32 * 4) + soff[i], Alo + gAo + kt + 4 * i);
            cp_async16(aBh + s * (ST_U32 * 4) + soff[i], Bhi + gBo + kt + 4 * i);
            cp_async16(aBl + s * (ST_U32 * 4) + soff[i], Blo + gBo + kt + 4 * i);
        }
        cp_commit();
    }

    int cur = 0;
    for (int c = 0; c < 16; ++c) {
        if (c + 2 < 16) cp_wait<1>();
        else            cp_wait<0>();
        __syncthreads();

        const uint32_t sbA = cur * (ST_U32 * 4);
        #pragma unroll
        for (int kk2 = 0; kk2 < 2; ++kk2) {
            uint32_t ah[4][4], al[4][4];
            #pragma unroll
            for (int mt = 0; mt < 4; ++mt) {
                ldsm_x4(ah[mt], aAh + sbA + offA[kk2] + mt * 1024u);
                ldsm_x4(al[mt], aAl + sbA + offA[kk2] + mt * 1024u);
            }
            #pragma unroll
            for (int nt = 0; nt < 4; ++nt) {
                uint32_t bh[2], bl[2];
                ldsm_x2(bh, aBh + sbA + offB[kk2] + nt * 512u);
                ldsm_x2(bl, aBl + sbA + offB[kk2] + nt * 512u);
                #pragma unroll
                for (int mt = 0; mt < 4; ++mt)
                    mma_bf16(acc[mt][nt], ah[mt], bh);
                #pragma unroll
                for (int mt = 0; mt < 4; ++mt)
                    mma_bf16(acc[mt][nt], ah[mt], bl);
                #pragma unroll
                for (int mt = 0; mt < 4; ++mt)
                    mma_bf16(acc[mt][nt], al[mt], bh);
            }
        }

        if (c + 2 < 16) {
            const int nb = (cur + 2 >= 3) ? cur - 1 : cur + 2;
            const int kt = (c + 2) * 16;
            #pragma unroll
            for (int i = 0; i < 2; ++i) {
                cp_async16(aAh + nb * (ST_U32 * 4) + soff[i], Ahi + gAo + kt + 4 * i);
                cp_async16(aAl + nb * (ST_U32 * 4) + soff[i], Alo + gAo + kt + 4 * i);
                cp_async16(aBh + nb * (ST_U32 * 4) + soff[i], Bhi + gBo + kt + 4 * i);
                cp_async16(aBl + nb * (ST_U32 * 4) + soff[i], Blo + gBo + kt + 4 * i);
            }
            cp_commit();
        }
        cur = (cur + 1 >= 3) ? 0 : cur + 1;
    }

    // ---- epilogue (unchanged) ----
    #pragma unroll
    for (int nt = 0; nt < 4; ++nt) {
        const int c0 = N0 + warpN * 32 + nt * 8 + c4 * 2;
        const float2 bv = *(const float2*)&bias[c0];
        if (MODE == 0) {
            const int h   = c0 / 96;
            const int rem = c0 - h * 96;
            const int sel = rem >> 5;
            const int d   = rem & 31;
            float* dst = (sel == 0) ? g_Q : (sel == 1) ? g_K : g_V;
            const float m = (sel == 0) ? ATT_SCALE : 1.0f;
            #pragma unroll
            for (int mt = 0; mt < 4; ++mt)
                #pragma unroll
                for (int hh = 0; hh < 2; ++hh) {
                    const int t = M0 + warpM * 64 + mt * 16 + r4 + hh * 8;
                    const int bwin = t >> 6, n = t & 63;
                    const size_t off =
                        ((size_t)(bwin * HEADS + h) * NT + n) * HD + d;
                    float2 o;
                    o.x = (acc[mt][nt][hh * 2 + 0] + bv.x) * m;
                    o.y = (acc[mt][nt][hh * 2 + 1] + bv.y) * m;
                    *(float2*)&dst[off] = o;
                }
        } else {
            #pragma unroll
            for (int mt = 0; mt < 4; ++mt)
                #pragma unroll
                for (int hh = 0; hh < 2; ++hh) {
                    const int t = M0 + warpM * 64 + mt * 16 + r4 + hh * 8;
                    float2 o;
                    o.x = acc[mt][nt][hh * 2 + 0] + bv.x;
                    o.y = acc[mt][nt][hh * 2 + 1] + bv.y;
                    *(float2*)&Out[(size_t)t * CIN + c0] = o;
                }
        }
    }
}

// ----------------------------------------------------------------------------
// Attention (unchanged from passing round 12).
// ----------------------------------------------------------------------------
__global__ __launch_bounds__(128)
void attn_kernel(const float* __restrict__ mask,
                 const float* __restrict__ bias_table,
                 const int*   __restrict__ rel_index)
{
    __shared__ float    Qs[64 * 36];
    __shared__ float    Ks[64 * 36];
    __shared__ uint32_t VtHi[32 * 36];
    __shared__ uint32_t VtLo[32 * 36];

    const int bid = blockIdx.x;
    const int b   = bid >> 4;
    const int h   = bid & 15;
    const int w   = b & 255;
    const int tid = threadIdx.x;
    const int wid = tid >> 5, lane = tid & 31;
    const int r4  = lane >> 2, c4 = lane & 3;

    const float* qp = g_Q + (size_t)bid * (NT * HD);
    const float* kp = g_K + (size_t)bid * (NT * HD);
    const float* vp = g_V + (size_t)bid * (NT * HD);

    {
        const int row = tid >> 1, half = (tid & 1) << 4;
        #pragma unroll
        for (int i = 0; i < 4; ++i) {
            *(float4*)&Qs[row * 36 + half + 4 * i] =
                *(const float4*)(qp + row * 32 + half + 4 * i);
            *(float4*)&Ks[row * 36 + half + 4 * i] =
                *(const float4*)(kp + row * 32 + half + 4 * i);
        }
        const int jp = tid >> 2, d0 = (tid & 3) << 3;
        float4 v00 = *(const float4*)(vp + (2 * jp) * 32 + d0);
        float4 v01 = *(const float4*)(vp + (2 * jp) * 32 + d0 + 4);
        float4 v10 = *(const float4*)(vp + (2 * jp + 1) * 32 + d0);
        float4 v11 = *(const float4*)(vp + (2 * jp + 1) * 32 + d0 + 4);
        uint32_t hh, ll;
        bf16_split2(make_float2(v00.x, v10.x), hh, ll);
        VtHi[(d0 + 0) * 36 + jp] = hh; VtLo[(d0 + 0) * 36 + jp] = ll;
        bf16_split2(make_float2(v00.y, v10.y), hh, ll);
        VtHi[(d0 + 1) * 36 + jp] = hh; VtLo[(d0 + 1) * 36 + jp] = ll;
        bf16_split2(make_float2(v00.z, v10.z), hh, ll);
        VtHi[(d0 + 2) * 36 + jp] = hh; VtLo[(d0 + 2) * 36 + jp] = ll;
        bf16_split2(make_float2(v00.w, v10.w), hh, ll);
        VtHi[(d0 + 3) * 36 + jp] = hh; VtLo[(d0 + 3) * 36 + jp] = ll;
        bf16_split2(make_float2(v01.x, v11.x), hh, ll);
        VtHi[(d0 + 4) * 36 + jp] = hh; VtLo[(d0 + 4) * 36 + jp] = ll;
        bf16_split2(make_float2(v01.y, v11.y), hh, ll);
        VtHi[(d0 + 5) * 36 + jp] = hh; VtLo[(d0 + 5) * 36 + jp] = ll;
        bf16_split2(make_float2(v01.z, v11.z), hh, ll);
        VtHi[(d0 + 6) * 36 + jp] = hh; VtLo[(d0 + 6) * 36 + jp] = ll;
        bf16_split2(make_float2(v01.w, v11.w), hh, ll);
        VtHi[(d0 + 7) * 36 + jp] = hh; VtLo[(d0 + 7) * 36 + jp] = ll;
    }
    __syncthreads();

    const int rm = wid * 16;
    const int i0 = rm + r4, i1 = i0 + 8;
    float acc[8][4] = {};
    #pragma unroll
    for (int kk = 0; kk < 4; ++kk) {
        uint32_t a[4];
        const uint32_t* pa = (const uint32_t*)&Qs[(rm + r4) * 36 + kk * 8 + c4];
        a[0] = pa[0]; a[1] = pa[8 * 36]; a[2] = pa[4]; a[3] = pa[8 * 36 + 4];
        #pragma unroll
        for (int nt = 0; nt < 8; ++nt) {
            const uint32_t* pb =
                (const uint32_t*)&Ks[(nt * 8 + r4) * 36 + kk * 8 + c4];
            uint32_t bf[2] = { pb[0], pb[4] };
            mma_tf32(acc[nt], a, bf);
        }
    }

    #pragma unroll
    for (int nt = 0; nt < 8; ++nt) {
        const int jc = nt * 8 + 2 * c4;
        const int2 rI0 = *(const int2*)&rel_index[i0 * 64 + jc];
        const int2 rI1 = *(const int2*)&rel_index[i1 * 64 + jc];
        const float2 m0 = *(const float2*)&mask[((size_t)w * 64 + i0) * 64 + jc];
        const float2 m1 = *(const float2*)&mask[((size_t)w * 64 + i1) * 64 + jc];
        acc[nt][0] += bias_table[rI0.x * HEADS + h] + m0.x;
        acc[nt][1] += bias_table[rI0.y * HEADS + h] + m0.y;
        acc[nt][2] += bias_table[rI1.x * HEADS + h] + m1.x;
        acc[nt][3] += bias_table[rI1.y * HEADS + h] + m1.y;
    }

    float mx0 = -3.0e38f, mx1 = -3.0e38f;
    #pragma unroll
    for (int nt = 0; nt < 8; ++nt) {
        mx0 = fmaxf(mx0, fmaxf(acc[nt][0], acc[nt][1]));
        mx1 = fmaxf(mx1, fmaxf(acc[nt][2], acc[nt][3]));
    }
    mx0 = fmaxf(mx0, __shfl_xor_sync(0xffffffffu, mx0, 1));
    mx0 = fmaxf(mx0, __shfl_xor_sync(0xffffffffu, mx0, 2));
    mx1 = fmaxf(mx1, __shfl_xor_sync(0xffffffffu, mx1, 1));
    mx1 = fmaxf(mx1, __shfl_xor_sync(0xffffffffu, mx1, 2));
    float s0 = 0.0f, s1 = 0.0f;
    #pragma unroll
    for (int nt = 0; nt < 8; ++nt) {
        acc[nt][0] = __expf(acc[nt][0] - mx0); s0 += acc[nt][0];
        acc[nt][1] = __expf(acc[nt][1] - mx0); s0 += acc[nt][1];
        acc[nt][2] = __expf(acc[nt][2] - mx1); s1 += acc[nt][2];
        acc[nt][3] = __expf(acc[nt][3] - mx1); s1 += acc[nt][3];
    }
    s0 += __shfl_xor_sync(0xffffffffu, s0, 1);
    s0 += __shfl_xor_sync(0xffffffffu, s0, 2);
    s1 += __shfl_xor_sync(0xffffffffu, s1, 1);
    s1 += __shfl_xor_sync(0xffffffffu, s1, 2);
    const float inv0 = 1.0f / s0, inv1 = 1.0f / s1;

    uint32_t ph[4][4], pl[4][4];
    #pragma unroll
    for (int ks = 0; ks < 4; ++ks) {
        bf16_split2(make_float2(acc[2 * ks][0] * inv0, acc[2 * ks][1] * inv0),
                    ph[ks][0], pl[ks][0]);
        bf16_split2(make_float2(acc[2 * ks][2] * inv1, acc[2 * ks][3] * inv1),
                    ph[ks][1], pl[ks][1]);
        bf16_split2(make_float2(acc[2 * ks + 1][0] * inv0, acc[2 * ks + 1][1] * inv0),
                    ph[ks][2], pl[ks][2]);
        bf16_split2(make_float2(acc[2 * ks + 1][2] * inv1, acc[2 * ks + 1][3] * inv1),
                    ph[ks][3], pl[ks][3]);
    }

    float acc2[4][4] = {};
    #pragma unroll
    for (int ks = 0; ks < 4; ++ks) {
        #pragma unroll
        for (int nt2 = 0; nt2 < 4; ++nt2) {
            const int vr = (nt2 * 8 + r4) * 36 + ks * 8 + c4;
            uint32_t bh[2] = { VtHi[vr], VtHi[vr + 4] };
            uint32_t bl[2] = { VtLo[vr], VtLo[vr + 4] };
            mma_bf16(acc2[nt2], ph[ks], bh);
            mma_bf16(acc2[nt2], ph[ks], bl);
            mma_bf16(acc2[nt2], pl[ks], bh);
        }
    }

    #pragma unroll
    for (int nt2 = 0; nt2 < 4; ++nt2) {
        const int d0 = nt2 * 8 + 2 * c4;
        const int kpair = h * 16 + (d0 >> 1);
        uint32_t hh, ll;
        bf16_split2(make_float2(acc2[nt2][0], acc2[nt2][1]), hh, ll);
        g_Ohi[((size_t)b * NT + i0) * KP + kpair] = hh;
        g_Olo[((size_t)b * NT + i0) * KP + kpair] = ll;
        bf16_split2(make_float2(acc2[nt2][2], acc2[nt2][3]), hh, ll);
        g_Ohi[((size_t)b * NT + i1) * KP + kpair] = hh;
        g_Olo[((size_t)b * NT + i1) * KP + kpair] = ll;
    }
}

// ----------------------------------------------------------------------------
extern "C" void kernel_launch(void* const* d_in, const int* in_sizes, int n_in,
                              void* d_out, int out_size)
{
    (void)in_sizes; (void)n_in; (void)out_size;
    const float* x          = (const float*)d_in[0];
    const float* mask       = (const float*)d_in[1];
    const float* qkv_w      = (const float*)d_in[2];
    const float* qkv_b      = (const float*)d_in[3];
    const float* proj_w     = (const float*)d_in[4];
    const float* proj_b     = (const float*)d_in[5];
    const float* bias_table = (const float*)d_in[6];
    const int*   rel_index  = (const int*)d_in[7];
    float* out = (float*)d_out;

    uint32_t *xhi, *xlo, *wh0, *wl0, *wh1, *wl1;
    float *wqkvT, *wprojT;
    cudaGetSymbolAddress((void**)&xhi, g_Xhi);
    cudaGetSymbolAddress((void**)&xlo, g_Xlo);
    cudaGetSymbolAddress((void**)&wh0, g_Wh0);
    cudaGetSymbolAddress((void**)&wl0, g_Wl0);
    cudaGetSymbolAddress((void**)&wh1, g_Wh1);
    cudaGetSymbolAddress((void**)&wl1, g_Wl1);
    cudaGetSymbolAddress((void**)&wqkvT, g_WqkvT);
    cudaGetSymbolAddress((void**)&wprojT, g_WprojT);

    cudaFuncSetAttribute((const void*)gemm_mma<0>,
                         cudaFuncAttributeMaxDynamicSharedMemorySize, SMEM_BYTES);
    cudaFuncSetAttribute((const void*)gemm_mma<1>,
                         cudaFuncAttributeMaxDynamicSharedMemorySize, SMEM_BYTES);

    transpose_w<0><<<dim3(48, 16), dim3(32, 8)>>>(qkv_w);
    transpose_w<1><<<dim3(16, 16), dim3(32, 8)>>>(proj_w);
    split_kernel<<<32768, 256>>>(x, xhi, xlo, BW * NT * CIN / 4);
    split_kernel<<<768, 256>>>(wqkvT, wh0, wl0, CQKV * CIN / 4);
    split_kernel<<<256, 256>>>(wprojT, wh1, wl1, CIN * CIN / 4);
    gemm_mma<0><<<dim3(12, 512), 256, SMEM_BYTES>>>(qkv_b, nullptr);
    attn_kernel<<<BW * HEADS, 128>>>(mask, bias_table, rel_index);
    gemm_mma<1><<<dim3(4, 512), 256, SMEM_BYTES>>>(proj_b, out);
}